// round 11
// baseline (speedup 1.0000x reference)
#include <cuda_runtime.h>
#include <math.h>

#define BIMG 4
#define HP   74
#define IMGPIX 6400
#define BT   576

// sqrt(log2(e) / (2*2.5^2)): arg = -(d*S)^2 == d^2 * -log2(e)/12.5
#define SCALE_S 0.33972874f
// -ln2 / 49
#define NEG_LN2_49 (-1.4145860827753985e-02f)
// ln(49 * sqrt(2*pi*2.5^2)) : folds the dropped per-element scale back in
#define ENT_OFF 5.7270496f

// shared floats: xs[11*80] | dvs[7*80] | S[7280] | W[3920] | red[320]
#define F_XS  0
#define F_DV  880
#define F_S   1440
#define F_W   8720
#define F_RED 12640
#define SMEM_BYTES ((12640 + 320) * 4)

__device__ __forceinline__ float ex2f(float x) {
    float y;
    asm("ex2.approx.f32 %0, %1;" : "=f"(y) : "f"(x));
    return y;
}
__device__ __forceinline__ float lg2f(float x) {
    float y;
    asm("lg2.approx.f32 %0, %1;" : "=f"(y) : "f"(x));
    return y;
}

// ---------------------------------------------------------------------------
// One block per (band py, image b): output row py+3. 296 blocks = 2 CTAs/SM.
//  1) load 11 input rows (float4), zero S boundary columns (xp>=74)
//  2) blur/round -> sharp -> division (exact op order), stored PRE-SCALED
//  3) KDE column sums: item (xp,dc), 49 exps, marginal U/V (no corrections);
//     direct entry U[r], mirror entry V[r] at column xc, offset 12-dc
//  4) prefix over dc -> 7 raw window sums W per (r,xp)   (no logs)
//  5) per window: 4 partial products of W, then 4 lg2 total; borders
// ---------------------------------------------------------------------------
__global__ __launch_bounds__(BT, 2)
void entropy_band_kernel(const float* __restrict__ x, float* __restrict__ out) {
    extern __shared__ float sm[];
    float* xs  = sm + F_XS;
    float* dvs = sm + F_DV;    // pre-scaled division values (7 rows x 80)
    float* S   = sm + F_S;     // [(r*80+xp)*13 + dc]
    float* W   = sm + F_W;     // raw window sums: [(r*7+c)*80 + xp]
    float* red = sm + F_RED;

    const int tid = threadIdx.x;
    const int py  = blockIdx.x;        // 0..73
    const int b   = blockIdx.y;        // 0..3
    const float* img = x + b * IMGPIX;
    float* ob = out + b * IMGPIX;

    // -- 1: input loads (first) + zero S boundary columns --------------------
    {
        float4* xs4 = (float4*)xs;
        const float4* img4 = (const float4*)img;
        for (int i = tid; i < 220; i += BT) {     // 11 rows * 20 float4
            int r = i / 20, c4 = i - r * 20;
            int row = py - 2 + r;
            xs4[i] = ((unsigned)row < 80u) ? img4[row * 20 + c4]
                                           : make_float4(0.f, 0.f, 0.f, 0.f);
        }
    }
    if (tid < 546) {                   // 7 r * 6 cols(74..79) * 13 dc
        int r  = tid / 78;
        int k2 = tid - r * 78;
        int xp = 74 + k2 / 13;
        int dc = k2 - (k2 / 13) * 13;
        S[(r * 80 + xp) * 13 + dc] = 0.0f;
    }
    __syncthreads();

    // -- 2: preprocessing (exact op order); store scaled ---------------------
    if (tid < 560) {
        int r = tid / 80, c = tid - (tid / 80) * 80;   // r = 0..6
        float sum = 0.0f;
        #pragma unroll
        for (int dy = 0; dy < 5; dy++) {
            const float* rowp = xs + (r + dy) * 80;
            #pragma unroll
            for (int dx = -2; dx <= 2; dx++) {
                int cc = c + dx;
                if ((unsigned)cc < 80u) sum = __fadd_rn(sum, rowp[cc]);
            }
        }
        float smooth = rintf(__fdiv_rn(sum, 25.0f));
        float cv     = xs[(r + 2) * 80 + c];
        float sharp  = rintf(fminf(fmaxf(
                          __fsub_rn(__fmul_rn(2.5f, cv), __fmul_rn(1.25f, smooth)),
                          0.0f), 255.0f));
        float divi   = rintf(fminf(fmaxf(
                          __fdiv_rn(__fmul_rn(sharp, 255.0f),
                                    __fadd_rn(smooth, 1e-8f)),
                          0.0f), 255.0f));
        dvs[tid] = __fmul_rn(divi, SCALE_S);
    }
    __syncthreads();

    // -- 3: KDE column sums via marginals (no boundary corrections) ----------
    if (tid < 560) {
        int dc = tid / 80;             // 0..6
        int xp = tid - dc * 80;        // 0..79
        int xc = xp - 6 + dc;          // <= xp
        if (xc >= 0) {
            float vA[7];
            #pragma unroll
            for (int a = 0; a < 7; a++) vA[a] = dvs[a * 80 + xp];
            float U[7], V[7];
            #pragma unroll
            for (int a = 0; a < 7; a++) U[a] = 0.0f;
            #pragma unroll
            for (int bb = 0; bb < 7; bb++) {
                float vb = dvs[bb * 80 + xc];
                float vsum = 0.0f;
                #pragma unroll
                for (int a = 0; a < 7; a++) {
                    float d = vA[a] - vb;
                    float e = ex2f(d * (-d));    // exp(-(d')^2), neg folds
                    U[a] += e;
                    vsum += e;
                }
                V[bb] = vsum;
            }
            #pragma unroll
            for (int r = 0; r < 7; r++)
                S[(r * 80 + xp) * 13 + dc] = U[r];
            if (dc < 6) {              // mirror: column xc, offset 12-dc
                #pragma unroll
                for (int r = 0; r < 7; r++)
                    S[(r * 80 + xc) * 13 + (12 - dc)] = V[r];
            }
        } else {
            #pragma unroll
            for (int r = 0; r < 7; r++)
                S[(r * 80 + xp) * 13 + dc] = 0.0f;
        }
    }
    __syncthreads();

    // -- 4: raw window sums via prefix (one item per thread) -----------------
    if (tid < 560) {
        const float* Sp = S + tid * 13;
        float pref[14];
        pref[0] = 0.0f;
        #pragma unroll
        for (int k = 0; k < 13; k++) pref[k + 1] = pref[k] + Sp[k];
        int r = tid / 80, xp = tid - (tid / 80) * 80;
        #pragma unroll
        for (int c = 0; c < 7; c++)
            W[(r * 7 + c) * 80 + xp] = pref[13 - c] - pref[6 - c];  // >= 1
    }
    __syncthreads();

    // -- 5: partial products per window (4 threads each), 4 lg2 at the end ---
    if (tid < 296) {
        float acc = 1.0f;
        int xw   = tid >> 2;               // 0..73
        int part = tid & 3;
        int i0 = (part == 0) ? 0 : (13 + 12 * (part - 1));
        int i1 = (part == 0) ? 13 : (i0 + 12);
        int r = i0 / 7, c = i0 - (i0 / 7) * 7;
        for (int i = i0; i < i1; i++) {
            acc *= W[(r * 7 + c) * 80 + xw + c];   // product <= 49^13
            if (++c == 7) { c = 0; r++; }
        }
        red[tid] = acc;
    }
    __syncthreads();

    if (tid < HP) {
        float t = lg2f(red[tid * 4])     + lg2f(red[tid * 4 + 1])
                + lg2f(red[tid * 4 + 2]) + lg2f(red[tid * 4 + 3]);
        ob[(py + 3) * 80 + (tid + 3)] = fmaf(t, NEG_LN2_49, ENT_OFF);
    }
    // column borders of this output row
    if (tid >= 96 && tid < 102) {
        int j = tid - 96;
        int col = (j < 3) ? j : (74 + j - 3);   // 0,1,2,77,78,79
        ob[(py + 3) * 80 + col] = 0.0f;
    }
    // top / bottom border rows
    if (py < 3  && tid >= 128 && tid < 208) ob[py * 80 + (tid - 128)] = 0.0f;
    if (py >= 71 && tid >= 128 && tid < 208) ob[(py + 6) * 80 + (tid - 128)] = 0.0f;
}

// ---------------------------------------------------------------------------
extern "C" void kernel_launch(void* const* d_in, const int* in_sizes, int n_in,
                              void* d_out, int out_size) {
    const float* x = (const float*)d_in[0];
    float* out     = (float*)d_out;

    cudaFuncSetAttribute(entropy_band_kernel,
                         cudaFuncAttributeMaxDynamicSharedMemorySize, SMEM_BYTES);
    dim3 grid(HP, BIMG);               // 296 blocks = 2 CTAs per SM
    entropy_band_kernel<<<grid, BT, SMEM_BYTES>>>(x, out);
}

// round 15
// speedup vs baseline: 1.0245x; 1.0245x over previous
#include <cuda_runtime.h>
#include <math.h>

#define BIMG 4
#define HP   74
#define IMGPIX 6400
#define BT   1024

// sqrt(log2(e) / (2*2.5^2)): arg = -(d*S)^2 == d^2 * -log2(e)/12.5
#define SCALE_S 0.33972874f
// -ln2 / 49
#define NEG_LN2_49 (-1.4145860827753985e-02f)
// ln(49 * sqrt(2*pi*2.5^2)) : folds the dropped per-element scale back in
#define ENT_OFF 5.7270496f

// shared floats: xs[960] | dvs[640] | S[2*7280] | W[2*3920] | red[640]
#define F_XS  0
#define F_DV  960
#define F_S   1600
#define F_W   16160
#define F_RED 24000
#define SMEM_BYTES ((24000 + 640) * 4)

__device__ __forceinline__ float ex2f(float x) {
    float y;
    asm("ex2.approx.f32 %0, %1;" : "=f"(y) : "f"(x));
    return y;
}
__device__ __forceinline__ float lg2f(float x) {
    float y;
    asm("lg2.approx.f32 %0, %1;" : "=f"(y) : "f"(x));
    return y;
}

// ---------------------------------------------------------------------------
// One block per (band pair g, image b): output rows py0+3, py0+4 (py0 = 2g).
// 1024 threads (32 warps). Phase 3 split: 1120 half-items (32 exps each);
// second loop pass covers half-items 1024..1119 on warps 0-2 (full warps).
//  1) load 12 input rows (float4); zero S boundary columns (xp>=74)
//  2) blur/round -> sharp -> division (exact op order), stored PRE-SCALED
//  3) KDE column sums: half-item = (xp,dc, bb-half); U marginals combined
//     via shfl_xor(1); boundary corrections local to the owning half
//  4) prefix over dc -> 7 raw window sums W per (band,r,xp)  (no logs)
//  5) per window: 4 partial products of W, then 4 lg2 total; borders
// ---------------------------------------------------------------------------
__global__ __launch_bounds__(BT, 1)
void entropy_pair_kernel(const float* __restrict__ x, float* __restrict__ out) {
    extern __shared__ float sm[];
    float* xs  = sm + F_XS;
    float* dvs = sm + F_DV;    // pre-scaled division values (8 rows x 80)
    float* S   = sm + F_S;     // [band][(r*80+xp)*13 + dc]
    float* W   = sm + F_W;     // raw window sums: [band][(r*7+c)*80 + xp]
    float* red = sm + F_RED;

    const int tid = threadIdx.x;
    const int g   = blockIdx.x;        // 0..36
    const int b   = blockIdx.y;        // 0..3
    const int py0 = 2 * g;
    const float* img = x + b * IMGPIX;
    float* ob = out + b * IMGPIX;

    // -- 1: input loads + zero S high-boundary columns (xp 74..79) ----------
    {
        float4* xs4 = (float4*)xs;
        const float4* img4 = (const float4*)img;
        for (int i = tid; i < 240; i += BT) {     // 12 rows * 20 float4
            int r = i / 20, c4 = i - r * 20;
            int row = py0 - 2 + r;
            xs4[i] = ((unsigned)row < 80u) ? img4[row * 20 + c4]
                                           : make_float4(0.f, 0.f, 0.f, 0.f);
        }
    }
    for (int i = tid; i < 1092; i += BT) {        // 2 bands * 7r * 6col * 13dc
        int h  = i / 546;
        int k  = i - h * 546;
        int r  = k / 78;
        int k2 = k - r * 78;
        int xp = 74 + k2 / 13;
        int dc = k2 - (k2 / 13) * 13;
        S[h * 7280 + (r * 80 + xp) * 13 + dc] = 0.0f;
    }
    __syncthreads();

    // -- 2: preprocessing (exact op order); store scaled ---------------------
    if (tid < 640) {
        int r = tid / 80, c = tid - (tid / 80) * 80;   // r = 0..7
        float sum = 0.0f;
        #pragma unroll
        for (int dy = 0; dy < 5; dy++) {
            const float* rowp = xs + (r + dy) * 80;
            #pragma unroll
            for (int dx = -2; dx <= 2; dx++) {
                int cc = c + dx;
                if ((unsigned)cc < 80u) sum = __fadd_rn(sum, rowp[cc]);
            }
        }
        float smooth = rintf(__fdiv_rn(sum, 25.0f));
        float cv     = xs[(r + 2) * 80 + c];
        float sharp  = rintf(fminf(fmaxf(
                          __fsub_rn(__fmul_rn(2.5f, cv), __fmul_rn(1.25f, smooth)),
                          0.0f), 255.0f));
        float divi   = rintf(fminf(fmaxf(
                          __fdiv_rn(__fmul_rn(sharp, 255.0f),
                                    __fadd_rn(smooth, 1e-8f)),
                          0.0f), 255.0f));
        dvs[tid] = __fmul_rn(divi, SCALE_S);
    }
    __syncthreads();

    // -- 3: KDE column sums, half-items over 2 loop passes -------------------
    for (int hi = tid; hi < 1120; hi += BT) {
        int item = hi >> 1;            // 0..559
        int half = hi & 1;             // bb base = half*4
        int dc   = item / 80;          // 0..6
        int xp   = item - dc * 80;     // 0..79
        int xc_r = xp - 6 + dc;        // may be negative
        bool valid = (xc_r >= 0);
        int xc = valid ? xc_r : 0;     // clamp for uniform execution

        float vA[8];
        #pragma unroll
        for (int a = 0; a < 8; a++) vA[a] = dvs[a * 80 + xp];

        float U[8], Vl[4], eA[8], eB0l[4], eB7l[4];
        #pragma unroll
        for (int a = 0; a < 8; a++) U[a] = 0.0f;

        #pragma unroll
        for (int k = 0; k < 4; k++) {
            int bb = half * 4 + k;
            float vb = dvs[bb * 80 + xc];
            float vsum = 0.0f;
            #pragma unroll
            for (int a = 0; a < 8; a++) {
                float d = vA[a] - vb;
                float e = ex2f(d * (-d));
                U[a] += e;
                vsum += e;
                if (a == 0) eB0l[k] = e;               // E[0][bb]
                if (a == 7) eB7l[k] = e;               // E[7][bb]
                if (k == 0 && half == 0) eA[a] = e;    // E[a][0]
                if (k == 3 && half == 1) eA[a] = e;    // E[a][7]
            }
            Vl[k] = vsum;
        }
        // combine row marginals across the two halves (adjacent lanes; both
        // passes cover full warps: 1024 = 32 warps, 96 = 3 warps)
        #pragma unroll
        for (int a = 0; a < 8; a++)
            U[a] += __shfl_xor_sync(0xffffffffu, U[a], 1);

        // direct entries: half1 writes band0 (s0), half0 writes band1 (s1)
        if (half) {
            #pragma unroll
            for (int r = 0; r < 7; r++)
                S[(r * 80 + xp) * 13 + dc] = valid ? (U[r] - eA[r]) : 0.0f;
        } else {
            #pragma unroll
            for (int r = 0; r < 7; r++)
                S[7280 + (r * 80 + xp) * 13 + dc] = valid ? (U[r + 1] - eA[r + 1]) : 0.0f;
        }
        // mirror entries at column xc, offset 12-dc (t0/t1), local V corrections
        if (valid && dc < 6) {
            int mo = xc * 13 + (12 - dc);
            #pragma unroll
            for (int k = 0; k < 4; k++) {
                int bb = half * 4 + k;
                if (bb <= 6)                       // t0[bb] = V[bb]-E[7][bb]
                    S[(bb * 80) * 13 + mo] = Vl[k] - eB7l[k];
                if (bb >= 1)                       // t1[bb-1] = V[bb]-E[0][bb]
                    S[7280 + ((bb - 1) * 80) * 13 + mo] = Vl[k] - eB0l[k];
            }
        }
    }
    __syncthreads();

    // -- 4: raw window sums via prefix ---------------------------------------
    for (int it = tid; it < 1120; it += BT) {
        int h  = it / 560;
        int rr = it - h * 560;         // r*80 + xp
        const float* Sp = S + h * 7280 + rr * 13;
        float pref[14];
        pref[0] = 0.0f;
        #pragma unroll
        for (int k = 0; k < 13; k++) pref[k + 1] = pref[k] + Sp[k];
        int r = rr / 80, xp = rr - (rr / 80) * 80;
        float* Wh = W + h * 3920;
        #pragma unroll
        for (int c = 0; c < 7; c++)
            Wh[(r * 7 + c) * 80 + xp] = pref[13 - c] - pref[6 - c];  // >= 1
    }
    __syncthreads();

    // -- 5: partial products per window (4 threads each), 4 lg2 at the end ---
    if (tid < 592) {
        float acc = 1.0f;
        int w    = tid >> 2;               // 0..147
        int part = tid & 3;
        int h    = w / 74;
        int xw   = w - h * 74;
        const float* Wh = W + h * 3920;
        int i0 = (part == 0) ? 0 : (13 + 12 * (part - 1));
        int i1 = (part == 0) ? 13 : (i0 + 12);
        int r = i0 / 7, c = i0 - (i0 / 7) * 7;
        for (int i = i0; i < i1; i++) {
            acc *= Wh[(r * 7 + c) * 80 + xw + c];   // product <= 49^13
            if (++c == 7) { c = 0; r++; }
        }
        red[tid] = acc;
    }
    __syncthreads();

    if (tid < 148) {
        int h  = tid / 74;
        int xw = tid - h * 74;
        float t = lg2f(red[tid * 4])     + lg2f(red[tid * 4 + 1])
                + lg2f(red[tid * 4 + 2]) + lg2f(red[tid * 4 + 3]);
        ob[(py0 + h + 3) * 80 + (xw + 3)] = fmaf(t, NEG_LN2_49, ENT_OFF);
    }
    // column borders of the two written rows: cols 0,1,2 and 77,78,79
    // (disjoint from the entropy writes above -> no race)
    if (tid >= 160 && tid < 172) {
        int k = tid - 160;
        int h = k / 6, j = k - h * 6;
        int col = (j < 3) ? j : (74 + j);      // j=3,4,5 -> 77,78,79
        ob[(py0 + h + 3) * 80 + col] = 0.0f;
    }
    // top / bottom border rows
    if (g == 0  && tid >= 256 && tid < 496) ob[tid - 256] = 0.0f;             // rows 0..2
    if (g == 36 && tid >= 256 && tid < 496) ob[77 * 80 + (tid - 256)] = 0.0f; // rows 77..79
}

// ---------------------------------------------------------------------------
extern "C" void kernel_launch(void* const* d_in, const int* in_sizes, int n_in,
                              void* d_out, int out_size) {
    const float* x = (const float*)d_in[0];
    float* out     = (float*)d_out;

    cudaFuncSetAttribute(entropy_pair_kernel,
                         cudaFuncAttributeMaxDynamicSharedMemorySize, SMEM_BYTES);
    dim3 grid(37, BIMG);               // 148 blocks = 1 per SM
    entropy_pair_kernel<<<grid, BT, SMEM_BYTES>>>(x, out);
}

// round 16
// speedup vs baseline: 1.2362x; 1.2066x over previous
#include <cuda_runtime.h>
#include <math.h>

#define BIMG 4
#define HP   74
#define IMGPIX 6400
#define BT   640

// sqrt(log2(e) / (2*2.5^2)): arg = -(d*S)^2 == d^2 * -log2(e)/12.5
#define SCALE_S 0.33972874f
// -ln2 / 49
#define NEG_LN2_49 (-1.4145860827753985e-02f)
// ln(49 * sqrt(2*pi*2.5^2)) : folds the dropped per-element scale back in
#define ENT_OFF 5.7270496f

// shared floats: xs[960] | dvs[640] | S2[7280 float2] | W2[3920 float2]
#define F_XS  0
#define F_DV  960
#define F_S   1600
#define F_W   16160
#define SMEM_BYTES (24000 * 4)

__device__ __forceinline__ float ex2f(float x) {
    float y;
    asm("ex2.approx.f32 %0, %1;" : "=f"(y) : "f"(x));
    return y;
}
__device__ __forceinline__ float lg2f(float x) {
    float y;
    asm("lg2.approx.f32 %0, %1;" : "=f"(y) : "f"(x));
    return y;
}

// ---------------------------------------------------------------------------
// One block per (band pair g, image b): output rows py0+3, py0+4 (py0 = 2g).
// 640 threads, 1 CTA/SM, 148 blocks. Bands interleaved as float2 throughout.
//  1) load 12 input rows (float4); zero S2; early border rows
//  2) blur/round -> sharp -> division (exact op order), stored PRE-SCALED
//  3) KDE column sums for both bands from shared 8x8 row-pair exps,
//     marginal U/V accumulation + boundary corrections; float2 writes
//  4) prefix over dc (float2) -> 7 raw window sums W2 per (r,xp)
//  5) 148 threads: 4 register product chains per window, 4 lg2, store
// ---------------------------------------------------------------------------
__global__ __launch_bounds__(BT, 1)
void entropy_pair_kernel(const float* __restrict__ x, float* __restrict__ out) {
    extern __shared__ float sm[];
    float*  xs  = sm + F_XS;
    float*  dvs = sm + F_DV;              // pre-scaled division values (8x80)
    float2* S2  = (float2*)(sm + F_S);    // [(r*80+xp)*13 + dc] -> (band0, band1)
    float2* W2  = (float2*)(sm + F_W);    // [(r*7+c)*80 + xp]   -> (band0, band1)

    const int tid = threadIdx.x;
    const int g   = blockIdx.x;        // 0..36
    const int b   = blockIdx.y;        // 0..3
    const int py0 = 2 * g;
    const float* img = x + b * IMGPIX;
    float* ob = out + b * IMGPIX;

    // -- 1: input loads first; zero S2; early border rows --------------------
    {
        float4* xs4 = (float4*)xs;
        const float4* img4 = (const float4*)img;
        for (int i = tid; i < 240; i += BT) {     // 12 rows * 20 float4
            int r = i / 20, c4 = i - r * 20;
            int row = py0 - 2 + r;
            xs4[i] = ((unsigned)row < 80u) ? img4[row * 20 + c4]
                                           : make_float4(0.f, 0.f, 0.f, 0.f);
        }
    }
    {
        float4* S4 = (float4*)S2;
        for (int i = tid; i < 14560 / 4; i += BT)
            S4[i] = make_float4(0.f, 0.f, 0.f, 0.f);
    }
    if (g == 0  && tid < 240) ob[tid] = 0.0f;             // rows 0..2
    if (g == 36 && tid < 240) ob[77 * 80 + tid] = 0.0f;   // rows 77..79
    __syncthreads();

    // -- 2: preprocessing (exact op order); store scaled ---------------------
    {
        int r = tid / 80, c = tid - (tid / 80) * 80;   // r = 0..7
        float sum = 0.0f;
        #pragma unroll
        for (int dy = 0; dy < 5; dy++) {
            const float* rowp = xs + (r + dy) * 80;
            #pragma unroll
            for (int dx = -2; dx <= 2; dx++) {
                int cc = c + dx;
                if ((unsigned)cc < 80u) sum = __fadd_rn(sum, rowp[cc]);
            }
        }
        float smooth = rintf(__fdiv_rn(sum, 25.0f));
        float cv     = xs[(r + 2) * 80 + c];
        float sharp  = rintf(fminf(fmaxf(
                          __fsub_rn(__fmul_rn(2.5f, cv), __fmul_rn(1.25f, smooth)),
                          0.0f), 255.0f));
        float divi   = rintf(fminf(fmaxf(
                          __fdiv_rn(__fmul_rn(sharp, 255.0f),
                                    __fadd_rn(smooth, 1e-8f)),
                          0.0f), 255.0f));
        dvs[tid] = __fmul_rn(divi, SCALE_S);
    }
    __syncthreads();

    // -- 3: KDE column sums for both bands (marginals + corrections) ---------
    if (tid < 560) {
        int dc = tid / 80;             // 0..6
        int xp = tid - dc * 80;        // 0..79
        int xc = xp - 6 + dc;          // <= xp
        if (xc >= 0) {
            float vA[8];
            #pragma unroll
            for (int a = 0; a < 8; a++) vA[a] = dvs[a * 80 + xp];
            float U[8], V[8];
            #pragma unroll
            for (int a = 0; a < 8; a++) { U[a] = 0.f; V[a] = 0.f; }
            float eA7[7], eA0[8], eB0[8], eB7[7];   // boundary exps
            #pragma unroll
            for (int bb = 0; bb < 8; bb++) {
                float vb = dvs[bb * 80 + xc];
                #pragma unroll
                for (int a = 0; a < 8; a++) {
                    float d = vA[a] - vb;
                    float e = ex2f(d * (-d));       // exp(-(d')^2), neg folds
                    U[a]  += e;
                    V[bb] += e;
                    if (bb == 7 && a < 7) eA7[a] = e;   // E[a][7]
                    if (bb == 0 && a > 0) eA0[a] = e;   // E[a][0]
                    if (a == 0 && bb > 0) eB0[bb] = e;  // E[0][bb]
                    if (a == 7 && bb < 7) eB7[bb] = e;  // E[7][bb]
                }
            }
            float2* Sd = S2 + xp * 13 + dc;
            #pragma unroll
            for (int r = 0; r < 7; r++)           // s0 = U[r]-E[r][7], s1 = U[r+1]-E[r+1][0]
                Sd[r * 1040] = make_float2(U[r] - eA7[r], U[r + 1] - eA0[r + 1]);
            if (dc < 6) {                         // mirror: column xc, offset 12-dc
                float2* Sm = S2 + xc * 13 + (12 - dc);
                #pragma unroll
                for (int r = 0; r < 7; r++)       // t0 = V[r]-E[7][r], t1 = V[r+1]-E[0][r+1]
                    Sm[r * 1040] = make_float2(V[r] - eB7[r], V[r + 1] - eB0[r + 1]);
            }
        }
    }
    __syncthreads();

    // -- 4: raw window sums via float2 prefix (one item per thread) ----------
    if (tid < 560) {                   // tid = r*80 + xp
        const float2* Sp = S2 + tid * 13;
        float2 pref[14];
        pref[0] = make_float2(0.f, 0.f);
        #pragma unroll
        for (int k = 0; k < 13; k++) {
            float2 s = Sp[k];
            pref[k + 1] = make_float2(pref[k].x + s.x, pref[k].y + s.y);
        }
        int r = tid / 80, xp = tid - (tid / 80) * 80;
        #pragma unroll
        for (int c = 0; c < 7; c++) {
            float2 w = make_float2(pref[13 - c].x - pref[6 - c].x,
                                   pref[13 - c].y - pref[6 - c].y);  // >= 1
            W2[(r * 7 + c) * 80 + xp] = w;
        }
    }
    __syncthreads();

    // -- 5: per-window 4 product chains in registers, 4 lg2, store -----------
    if (tid < 148) {
        int h  = tid / 74;             // band
        int xw = tid - h * 74;
        const float* Wf = (const float*)W2;
        float p0 = 1.f, p1 = 1.f, p2 = 1.f, p3 = 1.f;
        #pragma unroll
        for (int i = 0; i < 49; i++) {
            int r = i / 7, c = i - r * 7;
            float w = Wf[((r * 7 + c) * 80 + xw + c) * 2 + h];
            if      (i < 13) p0 *= w;          // products <= 49^13
            else if (i < 25) p1 *= w;
            else if (i < 37) p2 *= w;
            else             p3 *= w;
        }
        float t = lg2f(p0) + lg2f(p1) + lg2f(p2) + lg2f(p3);
        ob[(py0 + h + 3) * 80 + (xw + 3)] = fmaf(t, NEG_LN2_49, ENT_OFF);
    }
    // column borders of the two written rows: 0,1,2,77,78,79 (disjoint writes)
    if (tid >= 160 && tid < 172) {
        int k = tid - 160;
        int h = k / 6, j = k - h * 6;
        int col = (j < 3) ? j : (74 + j);
        ob[(py0 + h + 3) * 80 + col] = 0.0f;
    }
}

// ---------------------------------------------------------------------------
extern "C" void kernel_launch(void* const* d_in, const int* in_sizes, int n_in,
                              void* d_out, int out_size) {
    const float* x = (const float*)d_in[0];
    float* out     = (float*)d_out;

    cudaFuncSetAttribute(entropy_pair_kernel,
                         cudaFuncAttributeMaxDynamicSharedMemorySize, SMEM_BYTES);
    dim3 grid(37, BIMG);               // 148 blocks = 1 per SM
    entropy_pair_kernel<<<grid, BT, SMEM_BYTES>>>(x, out);
}